// round 2
// baseline (speedup 1.0000x reference)
#include <cuda_runtime.h>
#include <float.h>

#define NNODES 100000
#define F_IN   128
#define D1     256      // 8 heads * 32
#define HEADS  8
#define NCLS   40
#define NEG    0.2f

// ---------------- scratch (device globals; no allocation allowed) ----------
__device__ float g_h1[NNODES * D1];      // x @ W1
__device__ float g_acc1[NNODES * D1];    // layer-1 aggregation -> h2 after finalize
__device__ float g_ssrc1[NNODES * HEADS];
__device__ float g_sdst1[NNODES * HEADS];
__device__ float g_denom1[NNODES * HEADS];
__device__ float g_h3[NNODES * NCLS];    // h2 @ W2
__device__ float g_ssrc2[NNODES];
__device__ float g_sdst2[NNODES];
__device__ float g_denom2[NNODES];

__device__ __forceinline__ float lrelu(float v) { return v >= 0.f ? v : NEG * v; }

// ---------------- GEMM1: g_h1[M,256] = x[M,128] @ W1[128,256] ---------------
#define TM 64
#define TN 64
#define TK 16
#define APAD 4

__global__ __launch_bounds__(256) void gemm1_kernel(const float* __restrict__ A,
                                                    const float* __restrict__ B,
                                                    int M) {
    __shared__ float As[TK][TM + APAD];
    __shared__ float Bs[TK][TN + APAD];
    int tid = threadIdx.x;
    int tx = tid & 15, ty = tid >> 4;
    int rowBase = blockIdx.y * TM;
    int colBase = blockIdx.x * TN;
    float acc[4][4] = {};

    for (int k0 = 0; k0 < F_IN; k0 += TK) {
        {
            int r  = tid >> 2;          // 0..63
            int kg = (tid & 3) * 4;     // 0,4,8,12
            float4 v = make_float4(0.f, 0.f, 0.f, 0.f);
            int gr = rowBase + r;
            if (gr < M) v = *(const float4*)&A[(size_t)gr * F_IN + k0 + kg];
            As[kg + 0][r] = v.x; As[kg + 1][r] = v.y;
            As[kg + 2][r] = v.z; As[kg + 3][r] = v.w;
        }
        {
            int kk = tid >> 4;          // 0..15
            int c  = (tid & 15) * 4;
            float4 v = *(const float4*)&B[(size_t)(k0 + kk) * D1 + colBase + c];
            Bs[kk][c + 0] = v.x; Bs[kk][c + 1] = v.y;
            Bs[kk][c + 2] = v.z; Bs[kk][c + 3] = v.w;
        }
        __syncthreads();
#pragma unroll
        for (int kk = 0; kk < TK; kk++) {
            float a0 = As[kk][ty * 4 + 0], a1 = As[kk][ty * 4 + 1];
            float a2 = As[kk][ty * 4 + 2], a3 = As[kk][ty * 4 + 3];
            float b0 = Bs[kk][tx * 4 + 0], b1 = Bs[kk][tx * 4 + 1];
            float b2 = Bs[kk][tx * 4 + 2], b3 = Bs[kk][tx * 4 + 3];
            acc[0][0] += a0 * b0; acc[0][1] += a0 * b1; acc[0][2] += a0 * b2; acc[0][3] += a0 * b3;
            acc[1][0] += a1 * b0; acc[1][1] += a1 * b1; acc[1][2] += a1 * b2; acc[1][3] += a1 * b3;
            acc[2][0] += a2 * b0; acc[2][1] += a2 * b1; acc[2][2] += a2 * b2; acc[2][3] += a2 * b3;
            acc[3][0] += a3 * b0; acc[3][1] += a3 * b1; acc[3][2] += a3 * b2; acc[3][3] += a3 * b3;
        }
        __syncthreads();
    }
#pragma unroll
    for (int i = 0; i < 4; i++) {
        int gr = rowBase + ty * 4 + i;
        if (gr < M) {
            float4 o = make_float4(acc[i][0], acc[i][1], acc[i][2], acc[i][3]);
            *(float4*)&g_h1[(size_t)gr * D1 + colBase + tx * 4] = o;
        }
    }
}

// -------- scores1: per-node attention scores + denom self-init + zero acc ---
__global__ __launch_bounds__(256) void scores1_kernel(const float* __restrict__ asrc,
                                                      const float* __restrict__ adst,
                                                      int n) {
    int wid  = (blockIdx.x * blockDim.x + threadIdx.x) >> 5;
    int lane = threadIdx.x & 31;
    if (wid >= n) return;
    size_t base = (size_t)wid * D1 + lane * 8;
    float4 v0 = *(const float4*)&g_h1[base];
    float4 v1 = *(const float4*)&g_h1[base + 4];
    float4 a0 = *(const float4*)&asrc[lane * 8];
    float4 a1 = *(const float4*)&asrc[lane * 8 + 4];
    float4 d0 = *(const float4*)&adst[lane * 8];
    float4 d1 = *(const float4*)&adst[lane * 8 + 4];
    float ps = v0.x*a0.x + v0.y*a0.y + v0.z*a0.z + v0.w*a0.w
             + v1.x*a1.x + v1.y*a1.y + v1.z*a1.z + v1.w*a1.w;
    float pd = v0.x*d0.x + v0.y*d0.y + v0.z*d0.z + v0.w*d0.w
             + v1.x*d1.x + v1.y*d1.y + v1.z*d1.z + v1.w*d1.w;
    ps += __shfl_xor_sync(0xffffffffu, ps, 1);
    ps += __shfl_xor_sync(0xffffffffu, ps, 2);
    pd += __shfl_xor_sync(0xffffffffu, pd, 1);
    pd += __shfl_xor_sync(0xffffffffu, pd, 2);
    int h = lane >> 2;
    if ((lane & 3) == 0) {
        g_ssrc1[wid * HEADS + h] = ps;
        g_sdst1[wid * HEADS + h] = pd;
        g_denom1[wid * HEADS + h] = __expf(lrelu(ps + pd));  // self-loop term
    }
    float4 z = make_float4(0.f, 0.f, 0.f, 0.f);
    *(float4*)&g_acc1[base]     = z;
    *(float4*)&g_acc1[base + 4] = z;
}

// -------- edge softmax denominator pass (layer 1) ---------------------------
__global__ __launch_bounds__(256) void edge_sum1_kernel(const int* __restrict__ src,
                                                        const int* __restrict__ dst,
                                                        int E) {
    int idx = blockIdx.x * blockDim.x + threadIdx.x;
    if (idx >= E * HEADS) return;
    int e = idx >> 3, h = idx & 7;
    int s = src[e], d = dst[e];
    float ev = lrelu(g_ssrc1[s * HEADS + h] + g_sdst1[d * HEADS + h]);
    atomicAdd(&g_denom1[d * HEADS + h], __expf(ev));
}

// -------- edge aggregation (layer 1): warp per edge --------------------------
__global__ __launch_bounds__(256) void edge_aggr1_kernel(const int* __restrict__ src,
                                                         const int* __restrict__ dst,
                                                         int E) {
    int gtid = blockIdx.x * blockDim.x + threadIdx.x;
    int e = gtid >> 5;
    int lane = threadIdx.x & 31;
    if (e >= E) return;
    int s = src[e], d = dst[e];
    int h = lane >> 2;                       // lane covers channels [lane*8, lane*8+8) -> head lane/4
    float ev = lrelu(g_ssrc1[s * HEADS + h] + g_sdst1[d * HEADS + h]);
    float alpha = __expf(ev) / g_denom1[d * HEADS + h];
    size_t sb = (size_t)s * D1 + lane * 8;
    size_t db = (size_t)d * D1 + lane * 8;
    float4 v0 = *(const float4*)&g_h1[sb];
    float4 v1 = *(const float4*)&g_h1[sb + 4];
    float* o = &g_acc1[db];
    atomicAdd(o + 0, v0.x * alpha);
    atomicAdd(o + 1, v0.y * alpha);
    atomicAdd(o + 2, v0.z * alpha);
    atomicAdd(o + 3, v0.w * alpha);
    atomicAdd(o + 4, v1.x * alpha);
    atomicAdd(o + 5, v1.y * alpha);
    atomicAdd(o + 6, v1.z * alpha);
    atomicAdd(o + 7, v1.w * alpha);
}

// -------- finalize layer 1: add self contribution + bias + relu -> h2 -------
__global__ __launch_bounds__(256) void finalize1_kernel(const float* __restrict__ b1, int n) {
    int idx = blockIdx.x * blockDim.x + threadIdx.x;
    if (idx >= n * D1) return;
    int node = idx >> 8, c = idx & 255, h = c >> 5;
    float ss = g_ssrc1[node * HEADS + h], sd = g_sdst1[node * HEADS + h];
    float alpha = __expf(lrelu(ss + sd)) / g_denom1[node * HEADS + h];
    float v = g_acc1[idx] + g_h1[idx] * alpha + b1[c];
    g_acc1[idx] = v > 0.f ? v : 0.f;
}

// -------- GEMM2: g_h3[M,40] = h2[M,256] @ W2[256,40], W2 in smem ------------
__global__ __launch_bounds__(256) void gemm2_kernel(const float* __restrict__ B, int M) {
    __shared__ float Bs[D1 * NCLS];  // 40 KB
    for (int i = threadIdx.x; i < D1 * NCLS; i += 256) Bs[i] = B[i];
    __syncthreads();
    int warp = threadIdx.x >> 5, lane = threadIdx.x & 31;
    const int RPW = 16;
    int rowBase = (blockIdx.x * 8 + warp) * RPW;
    for (int i = 0; i < RPW; i++) {
        int row = rowBase + i;
        if (row >= M) return;
        const float* a = &g_acc1[(size_t)row * D1];
        float acc0 = 0.f, acc1 = 0.f;
#pragma unroll 8
        for (int k = 0; k < D1; k++) {
            float av = __ldg(a + k);
            acc0 += av * Bs[k * NCLS + lane];
            if (lane < 8) acc1 += av * Bs[k * NCLS + 32 + lane];
        }
        g_h3[(size_t)row * NCLS + lane] = acc0;
        if (lane < 8) g_h3[(size_t)row * NCLS + 32 + lane] = acc1;
    }
}

// -------- scores2 + denom self-init + zero output ---------------------------
__global__ __launch_bounds__(256) void scores2_kernel(const float* __restrict__ asrc,
                                                      const float* __restrict__ adst,
                                                      float* __restrict__ out, int n) {
    int wid  = (blockIdx.x * blockDim.x + threadIdx.x) >> 5;
    int lane = threadIdx.x & 31;
    if (wid >= n) return;
    size_t base = (size_t)wid * NCLS;
    float v0 = g_h3[base + lane];
    float v1 = (lane < 8) ? g_h3[base + 32 + lane] : 0.f;
    float a0 = asrc[lane], d0 = adst[lane];
    float a1 = (lane < 8) ? asrc[32 + lane] : 0.f;
    float d1 = (lane < 8) ? adst[32 + lane] : 0.f;
    float ps = v0 * a0 + v1 * a1;
    float pd = v0 * d0 + v1 * d1;
#pragma unroll
    for (int o = 16; o; o >>= 1) {
        ps += __shfl_xor_sync(0xffffffffu, ps, o);
        pd += __shfl_xor_sync(0xffffffffu, pd, o);
    }
    if (lane == 0) {
        g_ssrc2[wid] = ps;
        g_sdst2[wid] = pd;
        g_denom2[wid] = __expf(lrelu(ps + pd));  // self loop
    }
    out[base + lane] = 0.f;
    if (lane < 8) out[base + 32 + lane] = 0.f;
}

__global__ __launch_bounds__(256) void edge_sum2_kernel(const int* __restrict__ src,
                                                        const int* __restrict__ dst,
                                                        int E) {
    int e = blockIdx.x * blockDim.x + threadIdx.x;
    if (e >= E) return;
    int s = src[e], d = dst[e];
    float ev = lrelu(g_ssrc2[s] + g_sdst2[d]);
    atomicAdd(&g_denom2[d], __expf(ev));
}

__global__ __launch_bounds__(256) void edge_aggr2_kernel(const int* __restrict__ src,
                                                         const int* __restrict__ dst,
                                                         float* __restrict__ out, int E) {
    int gtid = blockIdx.x * blockDim.x + threadIdx.x;
    int e = gtid >> 5;
    int lane = threadIdx.x & 31;
    if (e >= E) return;
    int s = src[e], d = dst[e];
    float ev = lrelu(g_ssrc2[s] + g_sdst2[d]);
    float alpha = __expf(ev) / g_denom2[d];
    size_t sb = (size_t)s * NCLS, db = (size_t)d * NCLS;
    atomicAdd(&out[db + lane], g_h3[sb + lane] * alpha);
    if (lane < 8)
        atomicAdd(&out[db + 32 + lane], g_h3[sb + 32 + lane] * alpha);
}

// -------- finalize layer 2: self contribution + bias + log_softmax ----------
__global__ __launch_bounds__(256) void finalize2_kernel(const float* __restrict__ b2,
                                                        float* __restrict__ out, int n) {
    int wid  = (blockIdx.x * blockDim.x + threadIdx.x) >> 5;
    int lane = threadIdx.x & 31;
    if (wid >= n) return;
    float alpha = __expf(lrelu(g_ssrc2[wid] + g_sdst2[wid])) / g_denom2[wid];
    size_t base = (size_t)wid * NCLS;
    float v0 = out[base + lane] + g_h3[base + lane] * alpha + b2[lane];
    float v1 = -FLT_MAX;
    if (lane < 8)
        v1 = out[base + 32 + lane] + g_h3[base + 32 + lane] * alpha + b2[32 + lane];
    float m = fmaxf(v0, v1);
#pragma unroll
    for (int o = 16; o; o >>= 1) m = fmaxf(m, __shfl_xor_sync(0xffffffffu, m, o));
    float s = expf(v0 - m) + ((lane < 8) ? expf(v1 - m) : 0.f);
#pragma unroll
    for (int o = 16; o; o >>= 1) s += __shfl_xor_sync(0xffffffffu, s, o);
    float ls = logf(s);
    out[base + lane] = v0 - m - ls;
    if (lane < 8) out[base + 32 + lane] = v1 - m - ls;
}

// ---------------------------------------------------------------------------
extern "C" void kernel_launch(void* const* d_in, const int* in_sizes, int n_in,
                              void* d_out, int out_size) {
    const float* x     = (const float*)d_in[0];
    const int*   ei    = (const int*)d_in[1];      // JAX default x64 disabled -> int32
    const float* W1    = (const float*)d_in[2];
    const float* asrc1 = (const float*)d_in[3];
    const float* adst1 = (const float*)d_in[4];
    const float* b1    = (const float*)d_in[5];
    const float* W2    = (const float*)d_in[6];
    const float* asrc2 = (const float*)d_in[7];
    const float* adst2 = (const float*)d_in[8];
    const float* b2    = (const float*)d_in[9];
    float* out = (float*)d_out;

    int M = in_sizes[0] / F_IN;        // 100000
    int E = in_sizes[1] / 2;           // 1600000
    const int* src = ei;
    const int* dst = ei + E;

    // Layer 1
    {
        dim3 grid(D1 / TN, (M + TM - 1) / TM);
        gemm1_kernel<<<grid, 256>>>(x, W1, M);
    }
    {
        scores1_kernel<<<(M * 32 + 255) / 256, 256>>>(asrc1, adst1, M);
    }
    {
        long long tot = (long long)E * HEADS;
        edge_sum1_kernel<<<(int)((tot + 255) / 256), 256>>>(src, dst, E);
    }
    {
        long long tot = (long long)E * 32;
        edge_aggr1_kernel<<<(int)((tot + 255) / 256), 256>>>(src, dst, E);
    }
    {
        long long tot = (long long)M * D1;
        finalize1_kernel<<<(int)((tot + 255) / 256), 256>>>(b1, M);
    }

    // Layer 2
    {
        gemm2_kernel<<<(M + 127) / 128, 256>>>(W2, M);
    }
    {
        scores2_kernel<<<(M * 32 + 255) / 256, 256>>>(asrc2, adst2, out, M);
    }
    {
        edge_sum2_kernel<<<(E + 255) / 256, 256>>>(src, dst, E);
    }
    {
        long long tot = (long long)E * 32;
        edge_aggr2_kernel<<<(int)((tot + 255) / 256), 256>>>(src, dst, out, E);
    }
    {
        finalize2_kernel<<<(M * 32 + 255) / 256, 256>>>(b2, out, M);
    }
}

// round 3
// speedup vs baseline: 2.1308x; 2.1308x over previous
#include <cuda_runtime.h>
#include <float.h>

#define NNODES 100000
#define F_IN   128
#define D1     256      // 8 heads * 32
#define HEADS  8
#define NCLS   40
#define NEG    0.2f

// ---------------- scratch (device globals; no allocation allowed) ----------
__device__ __align__(16) float g_h1[NNODES * D1];      // x @ W1
__device__ __align__(16) float g_acc1[NNODES * D1];    // layer-1 unnormalized aggregation
__device__ float g_ssrc1[NNODES * HEADS];
__device__ float g_sdst1[NNODES * HEADS];
__device__ float g_denom1[NNODES * HEADS];
__device__ __align__(16) float g_h3[NNODES * NCLS];    // h2 @ W2
__device__ float g_ssrc2[NNODES];
__device__ float g_sdst2[NNODES];
__device__ float g_denom2[NNODES];

__device__ __forceinline__ float lrelu(float v) { return v >= 0.f ? v : NEG * v; }

__device__ __forceinline__ void red_add_v4(float* addr, float a, float b, float c, float d) {
    asm volatile("red.global.add.v4.f32 [%0], {%1,%2,%3,%4};"
                 :: "l"(addr), "f"(a), "f"(b), "f"(c), "f"(d) : "memory");
}
__device__ __forceinline__ void red_add_f32(float* addr, float v) {
    asm volatile("red.global.add.f32 [%0], %1;" :: "l"(addr), "f"(v) : "memory");
}

// ---------------- GEMM1: g_h1[M,256] = x[M,128] @ W1[128,256] ---------------
#define TM 64
#define TN 64
#define TK 16
#define APAD 4

__global__ __launch_bounds__(256) void gemm1_kernel(const float* __restrict__ A,
                                                    const float* __restrict__ B,
                                                    int M) {
    __shared__ float As[TK][TM + APAD];
    __shared__ float Bs[TK][TN + APAD];
    int tid = threadIdx.x;
    int tx = tid & 15, ty = tid >> 4;
    int rowBase = blockIdx.y * TM;
    int colBase = blockIdx.x * TN;
    float acc[4][4] = {};

    for (int k0 = 0; k0 < F_IN; k0 += TK) {
        {
            int r  = tid >> 2;
            int kg = (tid & 3) * 4;
            float4 v = make_float4(0.f, 0.f, 0.f, 0.f);
            int gr = rowBase + r;
            if (gr < M) v = *(const float4*)&A[(size_t)gr * F_IN + k0 + kg];
            As[kg + 0][r] = v.x; As[kg + 1][r] = v.y;
            As[kg + 2][r] = v.z; As[kg + 3][r] = v.w;
        }
        {
            int kk = tid >> 4;
            int c  = (tid & 15) * 4;
            float4 v = *(const float4*)&B[(size_t)(k0 + kk) * D1 + colBase + c];
            Bs[kk][c + 0] = v.x; Bs[kk][c + 1] = v.y;
            Bs[kk][c + 2] = v.z; Bs[kk][c + 3] = v.w;
        }
        __syncthreads();
#pragma unroll
        for (int kk = 0; kk < TK; kk++) {
            float a0 = As[kk][ty * 4 + 0], a1 = As[kk][ty * 4 + 1];
            float a2 = As[kk][ty * 4 + 2], a3 = As[kk][ty * 4 + 3];
            float b0 = Bs[kk][tx * 4 + 0], b1 = Bs[kk][tx * 4 + 1];
            float b2 = Bs[kk][tx * 4 + 2], b3 = Bs[kk][tx * 4 + 3];
            acc[0][0] += a0 * b0; acc[0][1] += a0 * b1; acc[0][2] += a0 * b2; acc[0][3] += a0 * b3;
            acc[1][0] += a1 * b0; acc[1][1] += a1 * b1; acc[1][2] += a1 * b2; acc[1][3] += a1 * b3;
            acc[2][0] += a2 * b0; acc[2][1] += a2 * b1; acc[2][2] += a2 * b2; acc[2][3] += a2 * b3;
            acc[3][0] += a3 * b0; acc[3][1] += a3 * b1; acc[3][2] += a3 * b2; acc[3][3] += a3 * b3;
        }
        __syncthreads();
    }
#pragma unroll
    for (int i = 0; i < 4; i++) {
        int gr = rowBase + ty * 4 + i;
        if (gr < M) {
            float4 o = make_float4(acc[i][0], acc[i][1], acc[i][2], acc[i][3]);
            *(float4*)&g_h1[(size_t)gr * D1 + colBase + tx * 4] = o;
        }
    }
}

// -------- scores1: per-node attention scores + denom self-init + zero acc ---
__global__ __launch_bounds__(256) void scores1_kernel(const float* __restrict__ asrc,
                                                      const float* __restrict__ adst,
                                                      int n) {
    int wid  = (blockIdx.x * blockDim.x + threadIdx.x) >> 5;
    int lane = threadIdx.x & 31;
    if (wid >= n) return;
    size_t base = (size_t)wid * D1 + lane * 8;
    float4 v0 = *(const float4*)&g_h1[base];
    float4 v1 = *(const float4*)&g_h1[base + 4];
    float4 a0 = *(const float4*)&asrc[lane * 8];
    float4 a1 = *(const float4*)&asrc[lane * 8 + 4];
    float4 d0 = *(const float4*)&adst[lane * 8];
    float4 d1 = *(const float4*)&adst[lane * 8 + 4];
    float ps = v0.x*a0.x + v0.y*a0.y + v0.z*a0.z + v0.w*a0.w
             + v1.x*a1.x + v1.y*a1.y + v1.z*a1.z + v1.w*a1.w;
    float pd = v0.x*d0.x + v0.y*d0.y + v0.z*d0.z + v0.w*d0.w
             + v1.x*d1.x + v1.y*d1.y + v1.z*d1.z + v1.w*d1.w;
    ps += __shfl_xor_sync(0xffffffffu, ps, 1);
    ps += __shfl_xor_sync(0xffffffffu, ps, 2);
    pd += __shfl_xor_sync(0xffffffffu, pd, 1);
    pd += __shfl_xor_sync(0xffffffffu, pd, 2);
    int h = lane >> 2;
    if ((lane & 3) == 0) {
        g_ssrc1[wid * HEADS + h] = ps;
        g_sdst1[wid * HEADS + h] = pd;
        g_denom1[wid * HEADS + h] = __expf(lrelu(ps + pd));  // self-loop term
    }
    float4 z = make_float4(0.f, 0.f, 0.f, 0.f);
    *(float4*)&g_acc1[base]     = z;
    *(float4*)&g_acc1[base + 4] = z;
}

// -------- fused edge pass (layer 1): warp per edge ---------------------------
// Accumulates UNNORMALIZED p*h[src] into g_acc1 and p into g_denom1.
__global__ __launch_bounds__(256) void edge1_kernel(const int* __restrict__ src,
                                                    const int* __restrict__ dst,
                                                    int E) {
    int gtid = blockIdx.x * blockDim.x + threadIdx.x;
    int e = gtid >> 5;
    int lane = threadIdx.x & 31;
    if (e >= E) return;
    int s = src[e], d = dst[e];
    int h = lane >> 2;                       // lane covers channels [lane*8, lane*8+8)
    float p = __expf(lrelu(g_ssrc1[s * HEADS + h] + g_sdst1[d * HEADS + h]));
    if ((lane & 3) == 0)
        red_add_f32(&g_denom1[d * HEADS + h], p);
    size_t sb = (size_t)s * D1 + lane * 8;
    size_t db = (size_t)d * D1 + lane * 8;
    float4 v0 = *(const float4*)&g_h1[sb];
    float4 v1 = *(const float4*)&g_h1[sb + 4];
    red_add_v4(&g_acc1[db],     v0.x * p, v0.y * p, v0.z * p, v0.w * p);
    red_add_v4(&g_acc1[db + 4], v1.x * p, v1.y * p, v1.z * p, v1.w * p);
}

// -------- finalize layer 1: add self term, normalize, bias, relu -> h2 ------
__global__ __launch_bounds__(256) void finalize1_kernel(const float* __restrict__ b1, int n) {
    int idx = blockIdx.x * blockDim.x + threadIdx.x;
    if (idx >= n * D1) return;
    int node = idx >> 8, c = idx & 255, h = c >> 5;
    float ss = g_ssrc1[node * HEADS + h], sd = g_sdst1[node * HEADS + h];
    float p_self = __expf(lrelu(ss + sd));
    float inv = __frcp_rn(g_denom1[node * HEADS + h]);
    float v = (g_acc1[idx] + g_h1[idx] * p_self) * inv + b1[c];
    g_acc1[idx] = v > 0.f ? v : 0.f;
}

// -------- GEMM2: g_h3[M,40] = h2[M,256] @ W2[256,40], W2 in smem ------------
__global__ __launch_bounds__(256) void gemm2_kernel(const float* __restrict__ B, int M) {
    __shared__ float Bs[D1 * NCLS];  // 40 KB
    for (int i = threadIdx.x; i < D1 * NCLS; i += 256) Bs[i] = B[i];
    __syncthreads();
    int warp = threadIdx.x >> 5, lane = threadIdx.x & 31;
    const int RPW = 16;
    int rowBase = (blockIdx.x * 8 + warp) * RPW;
    for (int i = 0; i < RPW; i++) {
        int row = rowBase + i;
        if (row >= M) return;
        const float* a = &g_acc1[(size_t)row * D1];
        float acc0 = 0.f, acc1 = 0.f;
#pragma unroll 8
        for (int k = 0; k < D1; k++) {
            float av = __ldg(a + k);
            acc0 += av * Bs[k * NCLS + lane];
            if (lane < 8) acc1 += av * Bs[k * NCLS + 32 + lane];
        }
        g_h3[(size_t)row * NCLS + lane] = acc0;
        if (lane < 8) g_h3[(size_t)row * NCLS + 32 + lane] = acc1;
    }
}

// -------- scores2 + denom self-init + zero output ---------------------------
__global__ __launch_bounds__(256) void scores2_kernel(const float* __restrict__ asrc,
                                                      const float* __restrict__ adst,
                                                      float* __restrict__ out, int n) {
    int wid  = (blockIdx.x * blockDim.x + threadIdx.x) >> 5;
    int lane = threadIdx.x & 31;
    if (wid >= n) return;
    size_t base = (size_t)wid * NCLS;
    float v0 = g_h3[base + lane];
    float v1 = (lane < 8) ? g_h3[base + 32 + lane] : 0.f;
    float a0 = asrc[lane], d0 = adst[lane];
    float a1 = (lane < 8) ? asrc[32 + lane] : 0.f;
    float d1 = (lane < 8) ? adst[32 + lane] : 0.f;
    float ps = v0 * a0 + v1 * a1;
    float pd = v0 * d0 + v1 * d1;
#pragma unroll
    for (int o = 16; o; o >>= 1) {
        ps += __shfl_xor_sync(0xffffffffu, ps, o);
        pd += __shfl_xor_sync(0xffffffffu, pd, o);
    }
    if (lane == 0) {
        g_ssrc2[wid] = ps;
        g_sdst2[wid] = pd;
        g_denom2[wid] = __expf(lrelu(ps + pd));  // self loop
    }
    out[base + lane] = 0.f;
    if (lane < 8) out[base + 32 + lane] = 0.f;
}

// -------- fused edge pass (layer 2): thread per (edge, chunk-of-4) ----------
__global__ __launch_bounds__(256) void edge2_kernel(const int* __restrict__ src,
                                                    const int* __restrict__ dst,
                                                    float* __restrict__ out,
                                                    int E) {
    int idx = blockIdx.x * blockDim.x + threadIdx.x;
    int e = idx / 10, c = idx - e * 10;   // NCLS/4 = 10 chunks
    if (e >= E) return;
    int s = src[e], d = dst[e];
    float p = __expf(lrelu(g_ssrc2[s] + g_sdst2[d]));
    if (c == 0) red_add_f32(&g_denom2[d], p);
    float4 v = *(const float4*)&g_h3[(size_t)s * NCLS + c * 4];
    red_add_v4(&out[(size_t)d * NCLS + c * 4], v.x * p, v.y * p, v.z * p, v.w * p);
}

// -------- finalize layer 2: self term, normalize, bias, log_softmax ---------
__global__ __launch_bounds__(256) void finalize2_kernel(const float* __restrict__ b2,
                                                        float* __restrict__ out, int n) {
    int wid  = (blockIdx.x * blockDim.x + threadIdx.x) >> 5;
    int lane = threadIdx.x & 31;
    if (wid >= n) return;
    float p_self = __expf(lrelu(g_ssrc2[wid] + g_sdst2[wid]));
    float inv = __frcp_rn(g_denom2[wid]);
    size_t base = (size_t)wid * NCLS;
    float v0 = (out[base + lane] + g_h3[base + lane] * p_self) * inv + b2[lane];
    float v1 = -FLT_MAX;
    if (lane < 8)
        v1 = (out[base + 32 + lane] + g_h3[base + 32 + lane] * p_self) * inv + b2[32 + lane];
    float m = fmaxf(v0, v1);
#pragma unroll
    for (int o = 16; o; o >>= 1) m = fmaxf(m, __shfl_xor_sync(0xffffffffu, m, o));
    float s = expf(v0 - m) + ((lane < 8) ? expf(v1 - m) : 0.f);
#pragma unroll
    for (int o = 16; o; o >>= 1) s += __shfl_xor_sync(0xffffffffu, s, o);
    float ls = logf(s);
    out[base + lane] = v0 - m - ls;
    if (lane < 8) out[base + 32 + lane] = v1 - m - ls;
}

// ---------------------------------------------------------------------------
extern "C" void kernel_launch(void* const* d_in, const int* in_sizes, int n_in,
                              void* d_out, int out_size) {
    const float* x     = (const float*)d_in[0];
    const int*   ei    = (const int*)d_in[1];      // JAX x64 disabled -> int32
    const float* W1    = (const float*)d_in[2];
    const float* asrc1 = (const float*)d_in[3];
    const float* adst1 = (const float*)d_in[4];
    const float* b1    = (const float*)d_in[5];
    const float* W2    = (const float*)d_in[6];
    const float* asrc2 = (const float*)d_in[7];
    const float* adst2 = (const float*)d_in[8];
    const float* b2    = (const float*)d_in[9];
    float* out = (float*)d_out;

    int M = in_sizes[0] / F_IN;        // 100000
    int E = in_sizes[1] / 2;           // 1600000
    const int* src = ei;
    const int* dst = ei + E;

    // Layer 1
    {
        dim3 grid(D1 / TN, (M + TM - 1) / TM);
        gemm1_kernel<<<grid, 256>>>(x, W1, M);
    }
    scores1_kernel<<<(M * 32 + 255) / 256, 256>>>(asrc1, adst1, M);
    {
        long long tot = (long long)E * 32;
        edge1_kernel<<<(int)((tot + 255) / 256), 256>>>(src, dst, E);
    }
    {
        long long tot = (long long)M * D1;
        finalize1_kernel<<<(int)((tot + 255) / 256), 256>>>(b1, M);
    }

    // Layer 2
    gemm2_kernel<<<(M + 127) / 128, 256>>>(W2, M);
    scores2_kernel<<<(M * 32 + 255) / 256, 256>>>(asrc2, adst2, out, M);
    {
        long long tot = (long long)E * 10;
        edge2_kernel<<<(int)((tot + 255) / 256), 256>>>(src, dst, out, E);
    }
    finalize2_kernel<<<(M * 32 + 255) / 256, 256>>>(b2, out, M);
}

// round 4
// speedup vs baseline: 3.3650x; 1.5792x over previous
#include <cuda_runtime.h>
#include <float.h>

#define NNODES 100000
#define F_IN   128
#define D1     256      // 8 heads * 32
#define HEADS  8
#define NCLS   40
#define NEG    0.2f
#define EMAX   1600000

// ---------------- scratch (device globals; no allocation allowed) ----------
__device__ __align__(16) float g_h1[NNODES * D1];      // x @ W1
__device__ __align__(16) float g_h2[NNODES * D1];      // layer-1 output
__device__ float g_ssrc1[NNODES * HEADS];
__device__ float g_sdst1[NNODES * HEADS];
__device__ float g_pself1[NNODES * HEADS];
__device__ __align__(16) float g_h3[NNODES * NCLS];    // h2 @ W2
__device__ float g_ssrc2[NNODES];
__device__ float g_sdst2[NNODES];
__device__ float g_pself2[NNODES];
// CSR (dst-binned edges)
__device__ int g_counts[NNODES];
__device__ int g_rowptr[NNODES + 1];
__device__ int g_cursor[NNODES];
__device__ int g_csr_src[EMAX];

__device__ __forceinline__ float lrelu(float v) { return v >= 0.f ? v : NEG * v; }

// ======================= CSR build ==========================================
__global__ __launch_bounds__(256) void zero_counts_kernel(int n) {
    int i = blockIdx.x * blockDim.x + threadIdx.x;
    if (i < n) g_counts[i] = 0;
}

__global__ __launch_bounds__(256) void hist_kernel(const int* __restrict__ dst, int E) {
    int e = blockIdx.x * blockDim.x + threadIdx.x;
    if (e < E) atomicAdd(&g_counts[dst[e]], 1);
}

// single-block exclusive scan over counts -> rowptr, cursor
__global__ __launch_bounds__(1024) void scan_kernel(int n) {
    __shared__ int carry;
    __shared__ int wsum[32];
    if (threadIdx.x == 0) carry = 0;
    __syncthreads();
    int lane = threadIdx.x & 31, w = threadIdx.x >> 5;
    for (int base = 0; base < n; base += 1024) {
        int i = base + threadIdx.x;
        int v = (i < n) ? g_counts[i] : 0;
        int x = v;
#pragma unroll
        for (int o = 1; o < 32; o <<= 1) {
            int y = __shfl_up_sync(0xffffffffu, x, o);
            if (lane >= o) x += y;
        }
        if (lane == 31) wsum[w] = x;
        __syncthreads();
        if (w == 0) {
            int s = wsum[lane];
#pragma unroll
            for (int o = 1; o < 32; o <<= 1) {
                int y = __shfl_up_sync(0xffffffffu, s, o);
                if (lane >= o) s += y;
            }
            wsum[lane] = s;
        }
        __syncthreads();
        int incl = x + (w > 0 ? wsum[w - 1] : 0) + carry;
        int excl = incl - v;
        if (i < n) { g_rowptr[i] = excl; g_cursor[i] = excl; }
        __syncthreads();
        if (threadIdx.x == 1023) carry = incl;
        __syncthreads();
    }
    if (threadIdx.x == 0) g_rowptr[n] = carry;
}

__global__ __launch_bounds__(256) void scatter_kernel(const int* __restrict__ src,
                                                      const int* __restrict__ dst, int E) {
    int e = blockIdx.x * blockDim.x + threadIdx.x;
    if (e >= E) return;
    int pos = atomicAdd(&g_cursor[dst[e]], 1);
    g_csr_src[pos] = src[e];
}

// ======== GEMM1 + fused scores: h1 = x@W1; also s_src/s_dst/p_self ==========
#define TM 64
#define TN 64
#define TK 16
#define APAD 4

__global__ __launch_bounds__(256) void gemm1_kernel(const float* __restrict__ A,
                                                    const float* __restrict__ B,
                                                    const float* __restrict__ asrc,
                                                    const float* __restrict__ adst,
                                                    int M) {
    __shared__ float As[TK][TM + APAD];
    __shared__ float Bs[TK][TN + APAD];
    __shared__ float sS[TM][2];
    __shared__ float sD[TM][2];
    int tid = threadIdx.x;
    int tx = tid & 15, ty = tid >> 4;
    int rowBase = blockIdx.y * TM;
    int colBase = blockIdx.x * TN;
    float acc[4][4] = {};

    if (tid < TM) { sS[tid][0] = 0.f; sS[tid][1] = 0.f; sD[tid][0] = 0.f; sD[tid][1] = 0.f; }

    for (int k0 = 0; k0 < F_IN; k0 += TK) {
        {
            int r  = tid >> 2;
            int kg = (tid & 3) * 4;
            float4 v = make_float4(0.f, 0.f, 0.f, 0.f);
            int gr = rowBase + r;
            if (gr < M) v = *(const float4*)&A[(size_t)gr * F_IN + k0 + kg];
            As[kg + 0][r] = v.x; As[kg + 1][r] = v.y;
            As[kg + 2][r] = v.z; As[kg + 3][r] = v.w;
        }
        {
            int kk = tid >> 4;
            int c  = (tid & 15) * 4;
            float4 v = *(const float4*)&B[(size_t)(k0 + kk) * D1 + colBase + c];
            Bs[kk][c + 0] = v.x; Bs[kk][c + 1] = v.y;
            Bs[kk][c + 2] = v.z; Bs[kk][c + 3] = v.w;
        }
        __syncthreads();
#pragma unroll
        for (int kk = 0; kk < TK; kk++) {
            float a0 = As[kk][ty * 4 + 0], a1 = As[kk][ty * 4 + 1];
            float a2 = As[kk][ty * 4 + 2], a3 = As[kk][ty * 4 + 3];
            float b0 = Bs[kk][tx * 4 + 0], b1 = Bs[kk][tx * 4 + 1];
            float b2 = Bs[kk][tx * 4 + 2], b3 = Bs[kk][tx * 4 + 3];
            acc[0][0] += a0 * b0; acc[0][1] += a0 * b1; acc[0][2] += a0 * b2; acc[0][3] += a0 * b3;
            acc[1][0] += a1 * b0; acc[1][1] += a1 * b1; acc[1][2] += a1 * b2; acc[1][3] += a1 * b3;
            acc[2][0] += a2 * b0; acc[2][1] += a2 * b1; acc[2][2] += a2 * b2; acc[2][3] += a2 * b3;
            acc[3][0] += a3 * b0; acc[3][1] += a3 * b1; acc[3][2] += a3 * b2; acc[3][3] += a3 * b3;
        }
        __syncthreads();
    }
    // write h1 tile
#pragma unroll
    for (int i = 0; i < 4; i++) {
        int gr = rowBase + ty * 4 + i;
        if (gr < M) {
            float4 o = make_float4(acc[i][0], acc[i][1], acc[i][2], acc[i][3]);
            *(float4*)&g_h1[(size_t)gr * D1 + colBase + tx * 4] = o;
        }
    }
    // fused scores: partial dots over this block's 64 cols (= heads 2bx, 2bx+1)
    float4 av = *(const float4*)&asrc[colBase + tx * 4];
    float4 dv = *(const float4*)&adst[colBase + tx * 4];
    int hh = tx >> 3;
#pragma unroll
    for (int i = 0; i < 4; i++) {
        float ps = acc[i][0]*av.x + acc[i][1]*av.y + acc[i][2]*av.z + acc[i][3]*av.w;
        float pd = acc[i][0]*dv.x + acc[i][1]*dv.y + acc[i][2]*dv.z + acc[i][3]*dv.w;
        atomicAdd(&sS[ty * 4 + i][hh], ps);
        atomicAdd(&sD[ty * 4 + i][hh], pd);
    }
    __syncthreads();
    if (tid < 2 * TM) {
        int row = tid >> 1, h2i = tid & 1;
        int gr = rowBase + row;
        if (gr < M) {
            int head = blockIdx.x * 2 + h2i;
            float ps = sS[row][h2i], pd = sD[row][h2i];
            g_ssrc1[gr * HEADS + head] = ps;
            g_sdst1[gr * HEADS + head] = pd;
            g_pself1[gr * HEADS + head] = __expf(lrelu(ps + pd));
        }
    }
}

// ======== aggregate1: node-per-warp, CSR, fused normalize+bias+relu ========
__global__ __launch_bounds__(256) void aggregate1_kernel(const float* __restrict__ b1, int M) {
    int wid  = (blockIdx.x * blockDim.x + threadIdx.x) >> 5;
    int lane = threadIdx.x & 31;
    if (wid >= M) return;
    int h = lane >> 2;
    float sdst_h = g_sdst1[wid * HEADS + h];
    float pself  = g_pself1[wid * HEADS + h];
    size_t nb = (size_t)wid * D1 + lane * 8;
    float4 a0 = *(const float4*)&g_h1[nb];
    float4 a1 = *(const float4*)&g_h1[nb + 4];
    float c0 = a0.x * pself, c1 = a0.y * pself, c2 = a0.z * pself, c3 = a0.w * pself;
    float c4 = a1.x * pself, c5 = a1.y * pself, c6 = a1.z * pself, c7 = a1.w * pself;
    float denom = pself;
    int beg = g_rowptr[wid], end = g_rowptr[wid + 1];
    for (int i = beg; i < end; i++) {
        int s = g_csr_src[i];
        float p = __expf(lrelu(g_ssrc1[s * HEADS + h] + sdst_h));
        size_t sb = (size_t)s * D1 + lane * 8;
        float4 v0 = *(const float4*)&g_h1[sb];
        float4 v1 = *(const float4*)&g_h1[sb + 4];
        c0 += v0.x * p; c1 += v0.y * p; c2 += v0.z * p; c3 += v0.w * p;
        c4 += v1.x * p; c5 += v1.y * p; c6 += v1.z * p; c7 += v1.w * p;
        denom += p;
    }
    float inv = __frcp_rn(denom);
    float4 bb0 = *(const float4*)&b1[lane * 8];
    float4 bb1 = *(const float4*)&b1[lane * 8 + 4];
    float4 o0, o1;
    o0.x = fmaxf(c0 * inv + bb0.x, 0.f); o0.y = fmaxf(c1 * inv + bb0.y, 0.f);
    o0.z = fmaxf(c2 * inv + bb0.z, 0.f); o0.w = fmaxf(c3 * inv + bb0.w, 0.f);
    o1.x = fmaxf(c4 * inv + bb1.x, 0.f); o1.y = fmaxf(c5 * inv + bb1.y, 0.f);
    o1.z = fmaxf(c6 * inv + bb1.z, 0.f); o1.w = fmaxf(c7 * inv + bb1.w, 0.f);
    *(float4*)&g_h2[nb]     = o0;
    *(float4*)&g_h2[nb + 4] = o1;
}

// ======== GEMM2 + fused scores2: h3 = h2@W2; s_src2/s_dst2/p_self2 =========
__global__ __launch_bounds__(256) void gemm2_kernel(const float* __restrict__ B,
                                                    const float* __restrict__ asrc,
                                                    const float* __restrict__ adst,
                                                    int M) {
    __shared__ float Bs[D1 * NCLS];  // 40 KB
    for (int i = threadIdx.x; i < D1 * NCLS; i += 256) Bs[i] = B[i];
    __syncthreads();
    int warp = threadIdx.x >> 5, lane = threadIdx.x & 31;
    float as0 = asrc[lane], ad0 = adst[lane];
    float as1 = (lane < 8) ? asrc[32 + lane] : 0.f;
    float ad1 = (lane < 8) ? adst[32 + lane] : 0.f;
    const int RPW = 16;
    int rowBase = (blockIdx.x * 8 + warp) * RPW;
    for (int i = 0; i < RPW; i++) {
        int row = rowBase + i;
        if (row >= M) return;
        const float* a = &g_h2[(size_t)row * D1];
        float acc0 = 0.f, acc1 = 0.f;
#pragma unroll 8
        for (int k = 0; k < D1; k++) {
            float av = __ldg(a + k);
            acc0 += av * Bs[k * NCLS + lane];
            if (lane < 8) acc1 += av * Bs[k * NCLS + 32 + lane];
        }
        g_h3[(size_t)row * NCLS + lane] = acc0;
        if (lane < 8) g_h3[(size_t)row * NCLS + 32 + lane] = acc1;
        float ps = acc0 * as0 + ((lane < 8) ? acc1 * as1 : 0.f);
        float pd = acc0 * ad0 + ((lane < 8) ? acc1 * ad1 : 0.f);
#pragma unroll
        for (int o = 16; o; o >>= 1) {
            ps += __shfl_xor_sync(0xffffffffu, ps, o);
            pd += __shfl_xor_sync(0xffffffffu, pd, o);
        }
        if (lane == 0) {
            g_ssrc2[row] = ps;
            g_sdst2[row] = pd;
            g_pself2[row] = __expf(lrelu(ps + pd));
        }
    }
}

// ======== aggregate2: node-per-warp, CSR, fused bias + log_softmax =========
__global__ __launch_bounds__(256) void aggregate2_kernel(const float* __restrict__ b2,
                                                         float* __restrict__ out, int M) {
    int wid  = (blockIdx.x * blockDim.x + threadIdx.x) >> 5;
    int lane = threadIdx.x & 31;
    if (wid >= M) return;
    float sdst = g_sdst2[wid];
    float pself = g_pself2[wid];
    size_t nb = (size_t)wid * NCLS;
    float v0 = g_h3[nb + lane] * pself;
    float v1 = (lane < 8) ? g_h3[nb + 32 + lane] * pself : 0.f;
    float denom = pself;
    int beg = g_rowptr[wid], end = g_rowptr[wid + 1];
    for (int i = beg; i < end; i++) {
        int s = g_csr_src[i];
        float p = __expf(lrelu(g_ssrc2[s] + sdst));
        size_t sb = (size_t)s * NCLS;
        v0 += p * g_h3[sb + lane];
        if (lane < 8) v1 += p * g_h3[sb + 32 + lane];
        denom += p;
    }
    float inv = __frcp_rn(denom);
    float z0 = v0 * inv + b2[lane];
    float z1 = (lane < 8) ? (v1 * inv + b2[32 + lane]) : -FLT_MAX;
    float m = fmaxf(z0, z1);
#pragma unroll
    for (int o = 16; o; o >>= 1) m = fmaxf(m, __shfl_xor_sync(0xffffffffu, m, o));
    float s = expf(z0 - m) + ((lane < 8) ? expf(z1 - m) : 0.f);
#pragma unroll
    for (int o = 16; o; o >>= 1) s += __shfl_xor_sync(0xffffffffu, s, o);
    float ls = logf(s);
    out[nb + lane] = z0 - m - ls;
    if (lane < 8) out[nb + 32 + lane] = z1 - m - ls;
}

// ---------------------------------------------------------------------------
extern "C" void kernel_launch(void* const* d_in, const int* in_sizes, int n_in,
                              void* d_out, int out_size) {
    const float* x     = (const float*)d_in[0];
    const int*   ei    = (const int*)d_in[1];      // JAX x64 disabled -> int32
    const float* W1    = (const float*)d_in[2];
    const float* asrc1 = (const float*)d_in[3];
    const float* adst1 = (const float*)d_in[4];
    const float* b1    = (const float*)d_in[5];
    const float* W2    = (const float*)d_in[6];
    const float* asrc2 = (const float*)d_in[7];
    const float* adst2 = (const float*)d_in[8];
    const float* b2    = (const float*)d_in[9];
    float* out = (float*)d_out;

    int M = in_sizes[0] / F_IN;        // 100000
    int E = in_sizes[1] / 2;           // 1600000
    const int* src = ei;
    const int* dst = ei + E;

    // CSR build (depends only on edge_index)
    zero_counts_kernel<<<(M + 255) / 256, 256>>>(M);
    hist_kernel<<<(E + 255) / 256, 256>>>(dst, E);
    scan_kernel<<<1, 1024>>>(M);
    scatter_kernel<<<(E + 255) / 256, 256>>>(src, dst, E);

    // Layer 1
    {
        dim3 grid(D1 / TN, (M + TM - 1) / TM);
        gemm1_kernel<<<grid, 256>>>(x, W1, asrc1, adst1, M);
    }
    aggregate1_kernel<<<(M * 32 + 255) / 256, 256>>>(b1, M);

    // Layer 2
    gemm2_kernel<<<(M + 127) / 128, 256>>>(W2, asrc2, adst2, M);
    aggregate2_kernel<<<(M * 32 + 255) / 256, 256>>>(b2, out, M);
}

// round 5
// speedup vs baseline: 3.7744x; 1.1217x over previous
#include <cuda_runtime.h>
#include <float.h>

#define NNODES 100000
#define F_IN   128
#define D1     256      // 8 heads * 32
#define HEADS  8
#define NCLS   40
#define NEG    0.2f
#define EMAX   1600000
#define SCAN_B 1024

// ---------------- scratch (device globals; no allocation allowed) ----------
__device__ __align__(16) float g_h1[NNODES * D1];      // x @ W1
__device__ __align__(16) float g_h2[NNODES * D1];      // layer-1 output
__device__ float g_ssrc1[NNODES * HEADS];
__device__ float g_sdst1[NNODES * HEADS];
__device__ float g_pself1[NNODES * HEADS];
__device__ __align__(16) float g_h3[NNODES * NCLS];    // h2 @ W2
__device__ float g_ssrc2[NNODES];
__device__ float g_sdst2[NNODES];
__device__ float g_pself2[NNODES];
// CSR (dst-binned edges)
__device__ int g_counts[NNODES];
__device__ int g_rowptr[NNODES + 1];
__device__ int g_cursor[NNODES];
__device__ int g_csr_src[EMAX];
__device__ int g_bsum[(NNODES + SCAN_B - 1) / SCAN_B];
__device__ int g_boff[(NNODES + SCAN_B - 1) / SCAN_B];

__device__ __forceinline__ float lrelu(float v) { return v >= 0.f ? v : NEG * v; }

// ======================= CSR build ==========================================
__global__ __launch_bounds__(256) void zero_counts_kernel(int n) {
    int i = blockIdx.x * blockDim.x + threadIdx.x;
    if (i < n) g_counts[i] = 0;
}

__global__ __launch_bounds__(256) void hist_kernel(const int* __restrict__ dst, int E) {
    int e = blockIdx.x * blockDim.x + threadIdx.x;
    if (e < E) atomicAdd(&g_counts[dst[e]], 1);
}

// pass A: per-block sums of counts
__global__ __launch_bounds__(SCAN_B) void scan_sums_kernel(int n) {
    __shared__ int ws[32];
    int i = blockIdx.x * SCAN_B + threadIdx.x;
    int v = (i < n) ? g_counts[i] : 0;
    int lane = threadIdx.x & 31, w = threadIdx.x >> 5;
    int s = v;
#pragma unroll
    for (int o = 16; o; o >>= 1) s += __shfl_xor_sync(0xffffffffu, s, o);
    if (lane == 0) ws[w] = s;
    __syncthreads();
    if (w == 0) {
        int t = ws[lane];
#pragma unroll
        for (int o = 16; o; o >>= 1) t += __shfl_xor_sync(0xffffffffu, t, o);
        if (lane == 0) g_bsum[blockIdx.x] = t;
    }
}

// pass B: exclusive scan of block sums (nb <= 1024), one block
__global__ __launch_bounds__(SCAN_B) void scan_offsets_kernel(int nb, int n) {
    __shared__ int ws[32];
    int lane = threadIdx.x & 31, w = threadIdx.x >> 5;
    int v = (threadIdx.x < nb) ? g_bsum[threadIdx.x] : 0;
    int x = v;
#pragma unroll
    for (int o = 1; o < 32; o <<= 1) {
        int y = __shfl_up_sync(0xffffffffu, x, o);
        if (lane >= o) x += y;
    }
    if (lane == 31) ws[w] = x;
    __syncthreads();
    if (w == 0) {
        int s = ws[lane];
#pragma unroll
        for (int o = 1; o < 32; o <<= 1) {
            int y = __shfl_up_sync(0xffffffffu, s, o);
            if (lane >= o) s += y;
        }
        ws[lane] = s;
    }
    __syncthreads();
    int incl = x + (w > 0 ? ws[w - 1] : 0);
    if (threadIdx.x < nb) g_boff[threadIdx.x] = incl - v;
    if (threadIdx.x == nb - 1) g_rowptr[n] = incl;
}

// pass C: per-block scan + offset -> rowptr, cursor
__global__ __launch_bounds__(SCAN_B) void scan_apply_kernel(int n) {
    __shared__ int ws[32];
    int i = blockIdx.x * SCAN_B + threadIdx.x;
    int v = (i < n) ? g_counts[i] : 0;
    int lane = threadIdx.x & 31, w = threadIdx.x >> 5;
    int x = v;
#pragma unroll
    for (int o = 1; o < 32; o <<= 1) {
        int y = __shfl_up_sync(0xffffffffu, x, o);
        if (lane >= o) x += y;
    }
    if (lane == 31) ws[w] = x;
    __syncthreads();
    if (w == 0) {
        int s = ws[lane];
#pragma unroll
        for (int o = 1; o < 32; o <<= 1) {
            int y = __shfl_up_sync(0xffffffffu, s, o);
            if (lane >= o) s += y;
        }
        ws[lane] = s;
    }
    __syncthreads();
    int excl = x - v + (w > 0 ? ws[w - 1] : 0) + g_boff[blockIdx.x];
    if (i < n) { g_rowptr[i] = excl; g_cursor[i] = excl; }
}

__global__ __launch_bounds__(256) void scatter_kernel(const int* __restrict__ src,
                                                      const int* __restrict__ dst, int E) {
    int e = blockIdx.x * blockDim.x + threadIdx.x;
    if (e >= E) return;
    int pos = atomicAdd(&g_cursor[dst[e]], 1);
    g_csr_src[pos] = src[e];
}

// ======== GEMM1 + fused scores: h1 = x@W1; also s_src/s_dst/p_self ==========
#define TM 64
#define TN 64
#define TK 16
#define APAD 4

__global__ __launch_bounds__(256) void gemm1_kernel(const float* __restrict__ A,
                                                    const float* __restrict__ B,
                                                    const float* __restrict__ asrc,
                                                    const float* __restrict__ adst,
                                                    int M) {
    __shared__ float As[TK][TM + APAD];
    __shared__ float Bs[TK][TN + APAD];
    __shared__ float sS[TM][2];
    __shared__ float sD[TM][2];
    int tid = threadIdx.x;
    int tx = tid & 15, ty = tid >> 4;
    int rowBase = blockIdx.y * TM;
    int colBase = blockIdx.x * TN;
    float acc[4][4] = {};

    if (tid < TM) { sS[tid][0] = 0.f; sS[tid][1] = 0.f; sD[tid][0] = 0.f; sD[tid][1] = 0.f; }

    for (int k0 = 0; k0 < F_IN; k0 += TK) {
        {
            int r  = tid >> 2;
            int kg = (tid & 3) * 4;
            float4 v = make_float4(0.f, 0.f, 0.f, 0.f);
            int gr = rowBase + r;
            if (gr < M) v = *(const float4*)&A[(size_t)gr * F_IN + k0 + kg];
            As[kg + 0][r] = v.x; As[kg + 1][r] = v.y;
            As[kg + 2][r] = v.z; As[kg + 3][r] = v.w;
        }
        {
            int kk = tid >> 4;
            int c  = (tid & 15) * 4;
            float4 v = *(const float4*)&B[(size_t)(k0 + kk) * D1 + colBase + c];
            Bs[kk][c + 0] = v.x; Bs[kk][c + 1] = v.y;
            Bs[kk][c + 2] = v.z; Bs[kk][c + 3] = v.w;
        }
        __syncthreads();
#pragma unroll
        for (int kk = 0; kk < TK; kk++) {
            float a0 = As[kk][ty * 4 + 0], a1 = As[kk][ty * 4 + 1];
            float a2 = As[kk][ty * 4 + 2], a3 = As[kk][ty * 4 + 3];
            float b0 = Bs[kk][tx * 4 + 0], b1 = Bs[kk][tx * 4 + 1];
            float b2 = Bs[kk][tx * 4 + 2], b3 = Bs[kk][tx * 4 + 3];
            acc[0][0] += a0 * b0; acc[0][1] += a0 * b1; acc[0][2] += a0 * b2; acc[0][3] += a0 * b3;
            acc[1][0] += a1 * b0; acc[1][1] += a1 * b1; acc[1][2] += a1 * b2; acc[1][3] += a1 * b3;
            acc[2][0] += a2 * b0; acc[2][1] += a2 * b1; acc[2][2] += a2 * b2; acc[2][3] += a2 * b3;
            acc[3][0] += a3 * b0; acc[3][1] += a3 * b1; acc[3][2] += a3 * b2; acc[3][3] += a3 * b3;
        }
        __syncthreads();
    }
#pragma unroll
    for (int i = 0; i < 4; i++) {
        int gr = rowBase + ty * 4 + i;
        if (gr < M) {
            float4 o = make_float4(acc[i][0], acc[i][1], acc[i][2], acc[i][3]);
            *(float4*)&g_h1[(size_t)gr * D1 + colBase + tx * 4] = o;
        }
    }
    float4 av = *(const float4*)&asrc[colBase + tx * 4];
    float4 dv = *(const float4*)&adst[colBase + tx * 4];
    int hh = tx >> 3;
#pragma unroll
    for (int i = 0; i < 4; i++) {
        float ps = acc[i][0]*av.x + acc[i][1]*av.y + acc[i][2]*av.z + acc[i][3]*av.w;
        float pd = acc[i][0]*dv.x + acc[i][1]*dv.y + acc[i][2]*dv.z + acc[i][3]*dv.w;
        atomicAdd(&sS[ty * 4 + i][hh], ps);
        atomicAdd(&sD[ty * 4 + i][hh], pd);
    }
    __syncthreads();
    if (tid < 2 * TM) {
        int row = tid >> 1, h2i = tid & 1;
        int gr = rowBase + row;
        if (gr < M) {
            int head = blockIdx.x * 2 + h2i;
            float ps = sS[row][h2i], pd = sD[row][h2i];
            g_ssrc1[gr * HEADS + head] = ps;
            g_sdst1[gr * HEADS + head] = pd;
            g_pself1[gr * HEADS + head] = __expf(lrelu(ps + pd));
        }
    }
}

// ======== aggregate1: 2 warps/node (128 ch each), CSR, unroll-2 =============
__global__ __launch_bounds__(256) void aggregate1_kernel(const float* __restrict__ b1, int M) {
    int gw   = (blockIdx.x * blockDim.x + threadIdx.x) >> 5;
    int node = gw >> 1;
    int half = gw & 1;
    int lane = threadIdx.x & 31;
    if (node >= M) return;
    int ch = half * 128 + lane * 4;          // 4 channels per lane
    int h  = ch >> 5;
    float sdst_h = g_sdst1[node * HEADS + h];
    float pself  = g_pself1[node * HEADS + h];
    size_t nb = (size_t)node * D1 + ch;
    float4 a = *(const float4*)&g_h1[nb];
    float c0 = a.x * pself, c1 = a.y * pself, c2 = a.z * pself, c3 = a.w * pself;
    float denom = pself;
    int beg = g_rowptr[node], end = g_rowptr[node + 1];
    int i = beg;
    for (; i + 2 <= end; i += 2) {
        int s0 = __ldg(&g_csr_src[i]);
        int s1 = __ldg(&g_csr_src[i + 1]);
        float p0 = __expf(lrelu(__ldg(&g_ssrc1[s0 * HEADS + h]) + sdst_h));
        float p1 = __expf(lrelu(__ldg(&g_ssrc1[s1 * HEADS + h]) + sdst_h));
        float4 v0 = *(const float4*)&g_h1[(size_t)s0 * D1 + ch];
        float4 v1 = *(const float4*)&g_h1[(size_t)s1 * D1 + ch];
        c0 += v0.x * p0 + v1.x * p1;
        c1 += v0.y * p0 + v1.y * p1;
        c2 += v0.z * p0 + v1.z * p1;
        c3 += v0.w * p0 + v1.w * p1;
        denom += p0 + p1;
    }
    if (i < end) {
        int s = __ldg(&g_csr_src[i]);
        float p = __expf(lrelu(__ldg(&g_ssrc1[s * HEADS + h]) + sdst_h));
        float4 v = *(const float4*)&g_h1[(size_t)s * D1 + ch];
        c0 += v.x * p; c1 += v.y * p; c2 += v.z * p; c3 += v.w * p;
        denom += p;
    }
    float inv = __frcp_rn(denom);
    float4 bb = *(const float4*)&b1[ch];
    float4 o;
    o.x = fmaxf(c0 * inv + bb.x, 0.f);
    o.y = fmaxf(c1 * inv + bb.y, 0.f);
    o.z = fmaxf(c2 * inv + bb.z, 0.f);
    o.w = fmaxf(c3 * inv + bb.w, 0.f);
    *(float4*)&g_h2[nb] = o;
}

// ======== GEMM2 + fused scores2: h3 = h2@W2; s_src2/s_dst2/p_self2 =========
__global__ __launch_bounds__(256) void gemm2_kernel(const float* __restrict__ B,
                                                    const float* __restrict__ asrc,
                                                    const float* __restrict__ adst,
                                                    int M) {
    __shared__ float Bs[D1 * NCLS];  // 40 KB
    for (int i = threadIdx.x; i < D1 * NCLS; i += 256) Bs[i] = B[i];
    __syncthreads();
    int warp = threadIdx.x >> 5, lane = threadIdx.x & 31;
    float as0 = asrc[lane], ad0 = adst[lane];
    float as1 = (lane < 8) ? asrc[32 + lane] : 0.f;
    float ad1 = (lane < 8) ? adst[32 + lane] : 0.f;
    const int RPW = 16;
    int rowBase = (blockIdx.x * 8 + warp) * RPW;
    for (int i = 0; i < RPW; i++) {
        int row = rowBase + i;
        if (row >= M) return;
        const float* a = &g_h2[(size_t)row * D1];
        float acc0 = 0.f, acc1 = 0.f;
#pragma unroll 4
        for (int k = 0; k < D1; k += 4) {
            float4 av = *(const float4*)(a + k);   // broadcast load
            acc0 += av.x * Bs[(k + 0) * NCLS + lane];
            acc0 += av.y * Bs[(k + 1) * NCLS + lane];
            acc0 += av.z * Bs[(k + 2) * NCLS + lane];
            acc0 += av.w * Bs[(k + 3) * NCLS + lane];
            if (lane < 8) {
                acc1 += av.x * Bs[(k + 0) * NCLS + 32 + lane];
                acc1 += av.y * Bs[(k + 1) * NCLS + 32 + lane];
                acc1 += av.z * Bs[(k + 2) * NCLS + 32 + lane];
                acc1 += av.w * Bs[(k + 3) * NCLS + 32 + lane];
            }
        }
        g_h3[(size_t)row * NCLS + lane] = acc0;
        if (lane < 8) g_h3[(size_t)row * NCLS + 32 + lane] = acc1;
        float ps = acc0 * as0 + ((lane < 8) ? acc1 * as1 : 0.f);
        float pd = acc0 * ad0 + ((lane < 8) ? acc1 * ad1 : 0.f);
#pragma unroll
        for (int o = 16; o; o >>= 1) {
            ps += __shfl_xor_sync(0xffffffffu, ps, o);
            pd += __shfl_xor_sync(0xffffffffu, pd, o);
        }
        if (lane == 0) {
            g_ssrc2[row] = ps;
            g_sdst2[row] = pd;
            g_pself2[row] = __expf(lrelu(ps + pd));
        }
    }
}

// ======== aggregate2: node-per-warp, CSR, unroll-2, fused log_softmax ======
__global__ __launch_bounds__(256) void aggregate2_kernel(const float* __restrict__ b2,
                                                         float* __restrict__ out, int M) {
    int wid  = (blockIdx.x * blockDim.x + threadIdx.x) >> 5;
    int lane = threadIdx.x & 31;
    if (wid >= M) return;
    float sdst = g_sdst2[wid];
    float pself = g_pself2[wid];
    size_t nb = (size_t)wid * NCLS;
    float v0 = g_h3[nb + lane] * pself;
    float v1 = (lane < 8) ? g_h3[nb + 32 + lane] * pself : 0.f;
    float denom = pself;
    int beg = g_rowptr[wid], end = g_rowptr[wid + 1];
    int i = beg;
    for (; i + 2 <= end; i += 2) {
        int s0 = __ldg(&g_csr_src[i]);
        int s1 = __ldg(&g_csr_src[i + 1]);
        float p0 = __expf(lrelu(__ldg(&g_ssrc2[s0]) + sdst));
        float p1 = __expf(lrelu(__ldg(&g_ssrc2[s1]) + sdst));
        size_t sb0 = (size_t)s0 * NCLS, sb1 = (size_t)s1 * NCLS;
        v0 += p0 * g_h3[sb0 + lane] + p1 * g_h3[sb1 + lane];
        if (lane < 8) v1 += p0 * g_h3[sb0 + 32 + lane] + p1 * g_h3[sb1 + 32 + lane];
        denom += p0 + p1;
    }
    if (i < end) {
        int s = __ldg(&g_csr_src[i]);
        float p = __expf(lrelu(__ldg(&g_ssrc2[s]) + sdst));
        size_t sb = (size_t)s * NCLS;
        v0 += p * g_h3[sb + lane];
        if (lane < 8) v1 += p * g_h3[sb + 32 + lane];
        denom += p;
    }
    float inv = __frcp_rn(denom);
    float z0 = v0 * inv + b2[lane];
    float z1 = (lane < 8) ? (v1 * inv + b2[32 + lane]) : -FLT_MAX;
    float m = fmaxf(z0, z1);
#pragma unroll
    for (int o = 16; o; o >>= 1) m = fmaxf(m, __shfl_xor_sync(0xffffffffu, m, o));
    float s = expf(z0 - m) + ((lane < 8) ? expf(z1 - m) : 0.f);
#pragma unroll
    for (int o = 16; o; o >>= 1) s += __shfl_xor_sync(0xffffffffu, s, o);
    float ls = logf(s);
    out[nb + lane] = z0 - m - ls;
    if (lane < 8) out[nb + 32 + lane] = z1 - m - ls;
}

// ---------------------------------------------------------------------------
extern "C" void kernel_launch(void* const* d_in, const int* in_sizes, int n_in,
                              void* d_out, int out_size) {
    const float* x     = (const float*)d_in[0];
    const int*   ei    = (const int*)d_in[1];      // JAX x64 disabled -> int32
    const float* W1    = (const float*)d_in[2];
    const float* asrc1 = (const float*)d_in[3];
    const float* adst1 = (const float*)d_in[4];
    const float* b1    = (const float*)d_in[5];
    const float* W2    = (const float*)d_in[6];
    const float* asrc2 = (const float*)d_in[7];
    const float* adst2 = (const float*)d_in[8];
    const float* b2    = (const float*)d_in[9];
    float* out = (float*)d_out;

    int M = in_sizes[0] / F_IN;        // 100000
    int E = in_sizes[1] / 2;           // 1600000
    const int* src = ei;
    const int* dst = ei + E;
    int NB = (M + SCAN_B - 1) / SCAN_B;

    // CSR build
    zero_counts_kernel<<<(M + 255) / 256, 256>>>(M);
    hist_kernel<<<(E + 255) / 256, 256>>>(dst, E);
    scan_sums_kernel<<<NB, SCAN_B>>>(M);
    scan_offsets_kernel<<<1, SCAN_B>>>(NB, M);
    scan_apply_kernel<<<NB, SCAN_B>>>(M);
    scatter_kernel<<<(E + 255) / 256, 256>>>(src, dst, E);

    // Layer 1
    {
        dim3 grid(D1 / TN, (M + TM - 1) / TM);
        gemm1_kernel<<<grid, 256>>>(x, W1, asrc1, adst1, M);
    }
    aggregate1_kernel<<<(M * 64 + 255) / 256, 256>>>(b1, M);

    // Layer 2
    gemm2_kernel<<<(M + 127) / 128, 256>>>(W2, asrc2, adst2, M);
    aggregate2_kernel<<<(M * 32 + 255) / 256, 256>>>(b2, out, M);
}